// round 1
// baseline (speedup 1.0000x reference)
#include <cuda_runtime.h>
#include <math.h>

// Problem constants
#define B_ROWS 32768
#define IN_DIM 128
#define HDIM   2048
#define DOUT   1536          // 64 splines * 24 params
#define NBINS  8
#define MIN_W  0.001f
#define MIN_H  0.001f
#define MIN_D  0.001f
// 1/sqrt(1 + 1e-5)
#define INV_BN 0.9999950000374997f

// Scratch (allocation-free rule: __device__ globals)
__device__ float g_h1[(size_t)B_ROWS * HDIM];
__device__ float g_h2[(size_t)B_ROWS * HDIM];
__device__ float g_params[(size_t)B_ROWS * DOUT];

// ---------------------------------------------------------------------------
// Tiled SGEMM: C[M x N] = epilogue(A @ W + bias)
//   A is M x K with row stride lda and k-element stride kstride (kstride=2
//   implements the even-column gather of x for GEMM1).
//   EPI == 0 : z = gamma*relu(z+bias)*INV_BN + beta   (MLP hidden layers)
//   EPI == 1 : z = z + bias                           (output layer)
// Block tile 128x128, K-tile 8, 256 threads, 8x8 per-thread microtile.
// All dims here are multiples of the tile sizes (no bounds checks needed).
// ---------------------------------------------------------------------------
template <int EPI>
__global__ __launch_bounds__(256) void sgemm_kernel(
    const float* __restrict__ A, int lda, int kstride,
    const float* __restrict__ W, int ldb,
    float* __restrict__ C, int ldc, int K,
    const float* __restrict__ bias,
    const float* __restrict__ gamma,
    const float* __restrict__ beta)
{
    __shared__ float As[8][128];
    __shared__ float Bs[8][128];

    const int tid = threadIdx.x;
    const int tx = tid & 15;        // 0..15 -> 8 cols each
    const int ty = tid >> 4;        // 0..15 -> 8 rows each
    const int row0 = blockIdx.y * 128;
    const int col0 = blockIdx.x * 128;

    // A staging: thread loads 4 scalars, one row, k-offsets a_k..a_k+3
    const int a_r = tid >> 1;
    const int a_k = (tid & 1) * 4;
    // B staging: thread loads one float4
    const int b_k = tid >> 5;
    const int b_n = (tid & 31) * 4;

    float acc[8][8];
#pragma unroll
    for (int i = 0; i < 8; ++i)
#pragma unroll
        for (int j = 0; j < 8; ++j) acc[i][j] = 0.0f;

    for (int kt = 0; kt < K; kt += 8) {
#pragma unroll
        for (int q = 0; q < 4; ++q) {
            As[a_k + q][a_r] =
                A[(size_t)(row0 + a_r) * lda + (size_t)(kt + a_k + q) * kstride];
        }
        *(float4*)&Bs[b_k][b_n] =
            *(const float4*)&W[(size_t)(kt + b_k) * ldb + col0 + b_n];
        __syncthreads();

#pragma unroll
        for (int kk = 0; kk < 8; ++kk) {
            float a[8], b[8];
            *(float4*)(a)     = *(const float4*)&As[kk][ty * 8];
            *(float4*)(a + 4) = *(const float4*)&As[kk][ty * 8 + 4];
            *(float4*)(b)     = *(const float4*)&Bs[kk][tx * 8];
            *(float4*)(b + 4) = *(const float4*)&Bs[kk][tx * 8 + 4];
#pragma unroll
            for (int i = 0; i < 8; ++i)
#pragma unroll
                for (int j = 0; j < 8; ++j)
                    acc[i][j] = fmaf(a[i], b[j], acc[i][j]);
        }
        __syncthreads();
    }

#pragma unroll
    for (int i = 0; i < 8; ++i) {
        const int r = row0 + ty * 8 + i;
#pragma unroll
        for (int j = 0; j < 8; ++j) {
            const int c = col0 + tx * 8 + j;
            float z = acc[i][j] + bias[c];
            if (EPI == 0) {
                z = fmaxf(z, 0.0f);
                z = gamma[c] * z * INV_BN + beta[c];
            }
            C[(size_t)r * ldc + c] = z;
        }
    }
}

// ---------------------------------------------------------------------------
// RQ-spline + scatter epilogue. One thread per (row, spline j).
// 256 threads/block = 4 rows; 64-lane shared reduction for log_det.
// Implements the reference formulas LITERALLY, including the
// bin_idx = clip(sum(x > cw[:-1]), 0, 7) convention (no -1).
// ---------------------------------------------------------------------------
__global__ __launch_bounds__(256) void spline_kernel(
    const float* __restrict__ x,
    const float* __restrict__ params,
    float* __restrict__ out,
    float* __restrict__ logdet)
{
    const int tid = threadIdx.x;
    const int row = blockIdx.x * 4 + (tid >> 6);
    const int j = tid & 63;

    const float* p = params + (size_t)row * DOUT + j * 24;

    float wr[NBINS], hr[NBINS], drw[NBINS];
#pragma unroll
    for (int k = 0; k < NBINS; ++k) wr[k] = p[k];
#pragma unroll
    for (int k = 0; k < NBINS; ++k) hr[k] = p[NBINS + k];
#pragma unroll
    for (int k = 0; k < NBINS; ++k) drw[k] = p[2 * NBINS + k];

    const float xi = x[(size_t)row * IN_DIM + 2 * j + 1];   // identity (odd cols)
    const float xt = x[(size_t)row * IN_DIM + 2 * j];       // transform pass-through

    // softmax(widths) -> w, cumulative cw[0..8]
    float cw[NBINS + 1], ch[NBINS + 1], dd[NBINS + 1];
    {
        float m = wr[0];
#pragma unroll
        for (int k = 1; k < NBINS; ++k) m = fmaxf(m, wr[k]);
        float e[NBINS], s = 0.0f;
#pragma unroll
        for (int k = 0; k < NBINS; ++k) { e[k] = expf(wr[k] - m); s += e[k]; }
        const float inv = 1.0f / s;
        cw[0] = 0.0f;
#pragma unroll
        for (int k = 0; k < NBINS; ++k) {
            const float w = MIN_W + (1.0f - MIN_W * NBINS) * e[k] * inv;
            cw[k + 1] = cw[k] + w;
        }
    }
    {
        float m = hr[0];
#pragma unroll
        for (int k = 1; k < NBINS; ++k) m = fmaxf(m, hr[k]);
        float e[NBINS], s = 0.0f;
#pragma unroll
        for (int k = 0; k < NBINS; ++k) { e[k] = expf(hr[k] - m); s += e[k]; }
        const float inv = 1.0f / s;
        ch[0] = 0.0f;
#pragma unroll
        for (int k = 0; k < NBINS; ++k) {
            const float h = MIN_H + (1.0f - MIN_H * NBINS) * e[k] * inv;
            ch[k + 1] = ch[k] + h;
        }
    }
#pragma unroll
    for (int k = 0; k < NBINS; ++k) {
        // stable softplus: max(x,0) + log1p(exp(-|x|))
        const float v = drw[k];
        dd[k] = MIN_D + (fmaxf(v, 0.0f) + log1pf(expf(-fabsf(v))));
    }
    dd[NBINS] = MIN_D;

    // bin index exactly as in reference
    int bin = 0;
#pragma unroll
    for (int k = 0; k < NBINS; ++k) bin += (xi > cw[k]) ? 1 : 0;
    bin = min(max(bin, 0), NBINS - 1);

    const float xl = cw[bin],     xr = cw[bin + 1];
    const float yl = ch[bin],     yr = ch[bin + 1];
    const float bw = xr - xl,     bh = yr - yl;
    const float dl = dd[bin],     dr = dd[bin + 1];

    float t = (xi - xl) / bw;
    t = fminf(fmaxf(t, 0.0f), 1.0f);

    const float num = bh * (dl * t * t + 2.0f * t * (1.0f - t));
    const float den = dl + (dr - dl) * t;
    const float yv = yl + num / den;

    const float ld = logf(bh)
                   + 2.0f * logf(2.0f * t * (1.0f - t) * dr + dl)
                   - logf(den);

    out[(size_t)row * IN_DIM + 2 * j]     = xt;
    out[(size_t)row * IN_DIM + 2 * j + 1] = yv;

    __shared__ float red[256];
    red[tid] = ld;
    __syncthreads();
    for (int s = 32; s > 0; s >>= 1) {
        if ((tid & 63) < s) red[tid] += red[tid + s];
        __syncthreads();
    }
    if ((tid & 63) == 0) logdet[row] = red[tid];
}

// ---------------------------------------------------------------------------
extern "C" void kernel_launch(void* const* d_in, const int* in_sizes, int n_in,
                              void* d_out, int out_size)
{
    const float* x   = (const float*)d_in[0];
    const float* W1  = (const float*)d_in[1];
    const float* b1  = (const float*)d_in[2];
    const float* g1  = (const float*)d_in[3];
    const float* be1 = (const float*)d_in[4];
    const float* W2  = (const float*)d_in[5];
    const float* b2  = (const float*)d_in[6];
    const float* g2  = (const float*)d_in[7];
    const float* be2 = (const float*)d_in[8];
    const float* W3  = (const float*)d_in[9];
    const float* b3  = (const float*)d_in[10];

    float* out    = (float*)d_out;
    float* logdet = out + (size_t)B_ROWS * IN_DIM;

    float *h1, *h2, *pp;
    cudaGetSymbolAddress((void**)&h1, g_h1);
    cudaGetSymbolAddress((void**)&h2, g_h2);
    cudaGetSymbolAddress((void**)&pp, g_params);

    // GEMM1: transform = x[:, 0::2]  (lda=128, kstride=2), K=64
    sgemm_kernel<0><<<dim3(HDIM / 128, B_ROWS / 128), 256>>>(
        x, IN_DIM, 2, W1, HDIM, h1, HDIM, 64, b1, g1, be1);

    // GEMM2: 2048 x 2048
    sgemm_kernel<0><<<dim3(HDIM / 128, B_ROWS / 128), 256>>>(
        h1, HDIM, 1, W2, HDIM, h2, HDIM, HDIM, b2, g2, be2);

    // GEMM3: 2048 x 1536 (+b3 only)
    sgemm_kernel<1><<<dim3(DOUT / 128, B_ROWS / 128), 256>>>(
        h2, HDIM, 1, W3, DOUT, pp, DOUT, HDIM, b3, (const float*)0, (const float*)0);

    // Spline + scatter + log_det
    spline_kernel<<<B_ROWS / 4, 256>>>(x, pp, out, logdet);
}

// round 6
// speedup vs baseline: 4.5757x; 4.5757x over previous
#include <cuda_runtime.h>
#include <math.h>
#include <stdint.h>

// ===========================================================================
// Problem constants
// ===========================================================================
#define B_ROWS 32768
#define IN_DIM 128
#define HDIM   2048
#define DOUT   1536
#define NBINS  8
#define MIN_W  0.001f
#define MIN_H  0.001f
#define MIN_D  0.001f
#define INV_BN 0.9999950000374997f

// Scratch (__device__ globals: allocation-free rule)
__device__ float g_h1[(size_t)B_ROWS * HDIM];
__device__ float g_h2[(size_t)B_ROWS * HDIM];
__device__ float g_params[(size_t)B_ROWS * DOUT];
__device__ float g_xe [(size_t)B_ROWS * 64];       // packed even cols of x (tf32-rounded)
__device__ float g_w1r[(size_t)64   * HDIM];       // tf32-rounded W1 [64,2048]
__device__ float g_w2r[(size_t)HDIM * HDIM];       // tf32-rounded W2
__device__ float g_w3r[(size_t)HDIM * DOUT];       // tf32-rounded W3

__device__ __forceinline__ float tf32r(float x) {
    uint32_t u;
    asm("cvt.rna.tf32.f32 %0, %1;" : "=r"(u) : "f"(x));
    return __uint_as_float(u);
}

__device__ __forceinline__ void mma_tf32(float* d, const uint32_t* a, const uint32_t* b) {
    asm volatile(
        "mma.sync.aligned.m16n8k8.row.col.f32.tf32.tf32.f32 "
        "{%0,%1,%2,%3}, {%4,%5,%6,%7}, {%8,%9}, {%0,%1,%2,%3};"
        : "+f"(d[0]), "+f"(d[1]), "+f"(d[2]), "+f"(d[3])
        : "r"(a[0]), "r"(a[1]), "r"(a[2]), "r"(a[3]), "r"(b[0]), "r"(b[1]));
}

__device__ __forceinline__ void cp_async16(uint32_t saddr, const void* gptr) {
    asm volatile("cp.async.cg.shared.global [%0], [%1], 16;" :: "r"(saddr), "l"(gptr));
}
#define CP_COMMIT() asm volatile("cp.async.commit_group;" ::: "memory")
#define CP_WAIT1()  asm volatile("cp.async.wait_group 1;" ::: "memory")

// ===========================================================================
// tf32 mma.sync GEMM: C[M x N] = epilogue(A[M x K] @ W[K x N] + bias)
//   Block tile 128x128, K-chunk 32, 3-stage cp.async pipeline, 256 threads.
//   8 warps in 2(M) x 4(N); warp tile 64x32 = 4x4 m16n8k8 mma tiles.
//   SMEM: As[128][36] (row-major, pad 36), Bs[32][132] (k-major, pad 132)
//   -> conflict-free fragment reads, 16B-aligned cp.async stores.
//   EPI 0: tf32round(gamma*relu(z+bias)*INV_BN + beta)    EPI 1: z + bias
// ===========================================================================
#define A_LD   36
#define B_LD   132
#define A_WORDS (128 * A_LD)          // 4608 words = 18432 B
#define B_WORDS (32 * B_LD)           // 4224 words = 16896 B
#define STAGE_WORDS (A_WORDS + B_WORDS)
#define SMEM_BYTES  (3 * STAGE_WORDS * 4)   // 105984 B

template <int EPI>
__global__ void __launch_bounds__(256, 2) mma_gemm(
    const float* __restrict__ A, int lda,
    const float* __restrict__ W, int ldb,
    float* __restrict__ C, int ldc, int K,
    const float* __restrict__ bias,
    const float* __restrict__ gamma,
    const float* __restrict__ beta)
{
    extern __shared__ float smem[];
    const int tid = threadIdx.x;
    const int wid = tid >> 5;
    const int lane = tid & 31;
    const int g = lane >> 2;           // 0..7
    const int c = lane & 3;            // 0..3
    const int wm = wid >> 2;           // 0..1 -> 64 rows
    const int wn = wid & 3;            // 0..3 -> 32 cols
    const int row0 = blockIdx.y * 128;
    const int col0 = blockIdx.x * 128;
    const int NK = K / 32;

    // cp.async staging assignments
    const int am = tid >> 3;                 // A: row 0..31 step (x4 iters -> 128)
    const int akq = (tid & 7) * 4;           // A: k quad 0..28
    const int bk = tid >> 5;                 // B: k 0..7 (x4 iters -> 32)
    const int bnq = (tid & 31) * 4;          // B: n quad

    uint32_t smem_u32;
    {
        uint64_t t = __cvta_generic_to_shared(smem);
        smem_u32 = (uint32_t)t;
    }

    float acc[4][4][4];
#pragma unroll
    for (int i = 0; i < 4; ++i)
#pragma unroll
        for (int j = 0; j < 4; ++j)
#pragma unroll
            for (int q = 0; q < 4; ++q) acc[i][j][q] = 0.0f;

    // ---- issue a stage's loads ----
    auto issue_stage = [&](int s, int kt) {
        const uint32_t abase = smem_u32 + (uint32_t)(s * STAGE_WORDS) * 4u;
        const uint32_t bbase = abase + A_WORDS * 4u;
#pragma unroll
        for (int it = 0; it < 4; ++it) {
            const int m = am + it * 32;
            cp_async16(abase + (uint32_t)(m * A_LD + akq) * 4u,
                       A + (size_t)(row0 + m) * lda + kt + akq);
        }
#pragma unroll
        for (int it = 0; it < 4; ++it) {
            const int k = bk + it * 8;
            cp_async16(bbase + (uint32_t)(k * B_LD + bnq) * 4u,
                       W + (size_t)(kt + k) * ldb + col0 + bnq);
        }
    };

    // prologue: prefetch stages 0,1 (always commit to keep group accounting)
#pragma unroll
    for (int j = 0; j < 2; ++j) {
        if (j < NK) issue_stage(j, j * 32);
        CP_COMMIT();
    }

    for (int i = 0; i < NK; ++i) {
        CP_WAIT1();
        __syncthreads();

        if (i + 2 < NK) issue_stage((i + 2) % 3, (i + 2) * 32);
        CP_COMMIT();

        const int s = i % 3;
        const float* As = smem + s * STAGE_WORDS;                 // [128][36]
        const float* Bs = smem + s * STAGE_WORDS + A_WORDS;       // [32][132]

#pragma unroll
        for (int ks = 0; ks < 32; ks += 8) {
            uint32_t af[4][4], bf[4][2];
#pragma unroll
            for (int mt = 0; mt < 4; ++mt) {
                const int rb = wm * 64 + mt * 16;
                af[mt][0] = __float_as_uint(As[(rb + g)     * A_LD + ks + c]);
                af[mt][1] = __float_as_uint(As[(rb + g + 8) * A_LD + ks + c]);
                af[mt][2] = __float_as_uint(As[(rb + g)     * A_LD + ks + c + 4]);
                af[mt][3] = __float_as_uint(As[(rb + g + 8) * A_LD + ks + c + 4]);
            }
#pragma unroll
            for (int nt = 0; nt < 4; ++nt) {
                const int nb = wn * 32 + nt * 8;
                bf[nt][0] = __float_as_uint(Bs[(ks + c)     * B_LD + nb + g]);
                bf[nt][1] = __float_as_uint(Bs[(ks + c + 4) * B_LD + nb + g]);
            }
#pragma unroll
            for (int mt = 0; mt < 4; ++mt)
#pragma unroll
                for (int nt = 0; nt < 4; ++nt)
                    mma_tf32(acc[mt][nt], af[mt], bf[nt]);
        }
        __syncthreads();
    }

    // ---- epilogue ----
#pragma unroll
    for (int mt = 0; mt < 4; ++mt) {
        const int r0 = row0 + wm * 64 + mt * 16 + g;
#pragma unroll
        for (int nt = 0; nt < 4; ++nt) {
            const int cb = col0 + wn * 32 + nt * 8 + 2 * c;
            float z[4];
            z[0] = acc[mt][nt][0] + __ldg(&bias[cb]);
            z[1] = acc[mt][nt][1] + __ldg(&bias[cb + 1]);
            z[2] = acc[mt][nt][2] + __ldg(&bias[cb]);
            z[3] = acc[mt][nt][3] + __ldg(&bias[cb + 1]);
            if (EPI == 0) {
                const float ga0 = __ldg(&gamma[cb]),     be0 = __ldg(&beta[cb]);
                const float ga1 = __ldg(&gamma[cb + 1]), be1v = __ldg(&beta[cb + 1]);
                z[0] = tf32r(ga0 * fmaxf(z[0], 0.0f) * INV_BN + be0);
                z[1] = tf32r(ga1 * fmaxf(z[1], 0.0f) * INV_BN + be1v);
                z[2] = tf32r(ga0 * fmaxf(z[2], 0.0f) * INV_BN + be0);
                z[3] = tf32r(ga1 * fmaxf(z[3], 0.0f) * INV_BN + be1v);
            }
            *(float2*)&C[(size_t)r0 * ldc + cb]       = make_float2(z[0], z[1]);
            *(float2*)&C[(size_t)(r0 + 8) * ldc + cb] = make_float2(z[2], z[3]);
        }
    }
}

// ===========================================================================
// Prep kernels
// ===========================================================================
__global__ void pack_x_kernel(const float* __restrict__ x, float* __restrict__ xe)
{
    const int i = blockIdx.x * 256 + threadIdx.x;   // over B_ROWS*64
    const int row = i >> 6, j = i & 63;
    xe[i] = tf32r(x[(size_t)row * IN_DIM + 2 * j]);
}

__global__ void round_kernel(const float* __restrict__ in, float* __restrict__ out, int n)
{
    const int i = blockIdx.x * 256 + threadIdx.x;
    if (i < n) out[i] = tf32r(in[i]);
}

// ===========================================================================
// RQ-spline + scatter epilogue
// ===========================================================================
__global__ __launch_bounds__(256) void spline_kernel(
    const float* __restrict__ x,
    const float* __restrict__ params,
    float* __restrict__ out,
    float* __restrict__ logdet)
{
    const int tid = threadIdx.x;
    const int row = blockIdx.x * 4 + (tid >> 6);
    const int j = tid & 63;
    const float* p = params + (size_t)row * DOUT + j * 24;

    float wr[NBINS], hr[NBINS], drw[NBINS];
#pragma unroll
    for (int k = 0; k < NBINS; ++k) wr[k] = p[k];
#pragma unroll
    for (int k = 0; k < NBINS; ++k) hr[k] = p[NBINS + k];
#pragma unroll
    for (int k = 0; k < NBINS; ++k) drw[k] = p[2 * NBINS + k];

    const float xi = x[(size_t)row * IN_DIM + 2 * j + 1];
    const float xt = x[(size_t)row * IN_DIM + 2 * j];

    float cw[NBINS + 1], ch[NBINS + 1], dd[NBINS + 1];
    {
        float m = wr[0];
#pragma unroll
        for (int k = 1; k < NBINS; ++k) m = fmaxf(m, wr[k]);
        float e[NBINS], s = 0.0f;
#pragma unroll
        for (int k = 0; k < NBINS; ++k) { e[k] = expf(wr[k] - m); s += e[k]; }
        const float inv = 1.0f / s;
        cw[0] = 0.0f;
#pragma unroll
        for (int k = 0; k < NBINS; ++k)
            cw[k + 1] = cw[k] + (MIN_W + (1.0f - MIN_W * NBINS) * e[k] * inv);
    }
    {
        float m = hr[0];
#pragma unroll
        for (int k = 1; k < NBINS; ++k) m = fmaxf(m, hr[k]);
        float e[NBINS], s = 0.0f;
#pragma unroll
        for (int k = 0; k < NBINS; ++k) { e[k] = expf(hr[k] - m); s += e[k]; }
        const float inv = 1.0f / s;
        ch[0] = 0.0f;
#pragma unroll
        for (int k = 0; k < NBINS; ++k)
            ch[k + 1] = ch[k] + (MIN_H + (1.0f - MIN_H * NBINS) * e[k] * inv);
    }
#pragma unroll
    for (int k = 0; k < NBINS; ++k) {
        const float v = drw[k];
        dd[k] = MIN_D + (fmaxf(v, 0.0f) + log1pf(expf(-fabsf(v))));
    }
    dd[NBINS] = MIN_D;

    int bin = 0;
#pragma unroll
    for (int k = 0; k < NBINS; ++k) bin += (xi > cw[k]) ? 1 : 0;
    bin = min(max(bin, 0), NBINS - 1);

    const float xl = cw[bin], xr = cw[bin + 1];
    const float yl = ch[bin], yr = ch[bin + 1];
    const float bw = xr - xl, bh = yr - yl;
    const float dl = dd[bin], dr = dd[bin + 1];

    float t = (xi - xl) / bw;
    t = fminf(fmaxf(t, 0.0f), 1.0f);

    const float num = bh * (dl * t * t + 2.0f * t * (1.0f - t));
    const float den = dl + (dr - dl) * t;
    const float yv = yl + num / den;
    const float ld = logf(bh) + 2.0f * logf(2.0f * t * (1.0f - t) * dr + dl) - logf(den);

    out[(size_t)row * IN_DIM + 2 * j] = xt;
    out[(size_t)row * IN_DIM + 2 * j + 1] = yv;

    __shared__ float red[256];
    red[tid] = ld;
    __syncthreads();
    for (int s = 32; s > 0; s >>= 1) {
        if ((tid & 63) < s) red[tid] += red[tid + s];
        __syncthreads();
    }
    if ((tid & 63) == 0) logdet[row] = red[tid];
}

// ===========================================================================
// Host side
// ===========================================================================
extern "C" void kernel_launch(void* const* d_in, const int* in_sizes, int n_in,
                              void* d_out, int out_size)
{
    const float* x   = (const float*)d_in[0];
    const float* W1  = (const float*)d_in[1];
    const float* b1  = (const float*)d_in[2];
    const float* g1  = (const float*)d_in[3];
    const float* be1 = (const float*)d_in[4];
    const float* W2  = (const float*)d_in[5];
    const float* b2  = (const float*)d_in[6];
    const float* g2  = (const float*)d_in[7];
    const float* be2 = (const float*)d_in[8];
    const float* W3  = (const float*)d_in[9];
    const float* b3  = (const float*)d_in[10];

    float* out    = (float*)d_out;
    float* logdet = out + (size_t)B_ROWS * IN_DIM;

    float *h1, *h2, *pp, *xe, *w1r, *w2r, *w3r;
    cudaGetSymbolAddress((void**)&h1,  g_h1);
    cudaGetSymbolAddress((void**)&h2,  g_h2);
    cudaGetSymbolAddress((void**)&pp,  g_params);
    cudaGetSymbolAddress((void**)&xe,  g_xe);
    cudaGetSymbolAddress((void**)&w1r, g_w1r);
    cudaGetSymbolAddress((void**)&w2r, g_w2r);
    cudaGetSymbolAddress((void**)&w3r, g_w3r);

    cudaFuncSetAttribute(mma_gemm<0>, cudaFuncAttributeMaxDynamicSharedMemorySize, SMEM_BYTES);
    cudaFuncSetAttribute(mma_gemm<1>, cudaFuncAttributeMaxDynamicSharedMemorySize, SMEM_BYTES);

    // Prep: pack x even cols (tf32) + round weights to tf32 (rna)
    pack_x_kernel<<<(B_ROWS * 64) / 256, 256>>>(x, xe);
    round_kernel<<<(64 * HDIM + 255) / 256, 256>>>(W1, w1r, 64 * HDIM);
    round_kernel<<<(HDIM * HDIM + 255) / 256, 256>>>(W2, w2r, HDIM * HDIM);
    round_kernel<<<(HDIM * DOUT + 255) / 256, 256>>>(W3, w3r, HDIM * DOUT);

    // GEMM1: [32768 x 64] @ [64 x 2048]
    mma_gemm<0><<<dim3(HDIM / 128, B_ROWS / 128), 256, SMEM_BYTES>>>(
        xe, 64, w1r, HDIM, h1, HDIM, 64, b1, g1, be1);
    // GEMM2: [32768 x 2048] @ [2048 x 2048]
    mma_gemm<0><<<dim3(HDIM / 128, B_ROWS / 128), 256, SMEM_BYTES>>>(
        h1, HDIM, w2r, HDIM, h2, HDIM, HDIM, b2, g2, be2);
    // GEMM3: [32768 x 2048] @ [2048 x 1536]
    mma_gemm<1><<<dim3(DOUT / 128, B_ROWS / 128), 256, SMEM_BYTES>>>(
        h2, HDIM, w3r, DOUT, pp, DOUT, HDIM, b3, (const float*)0, (const float*)0);

    // Spline + scatter + log_det
    spline_kernel<<<B_ROWS / 4, 256>>>(x, pp, out, logdet);
}

// round 7
// speedup vs baseline: 4.7340x; 1.0346x over previous
#include <cuda_runtime.h>
#include <math.h>
#include <stdint.h>

// ===========================================================================
// Problem constants
// ===========================================================================
#define B_ROWS 32768
#define IN_DIM 128
#define HDIM   2048
#define DOUT   1536
#define NBINS  8
#define MIN_W  0.001f
#define MIN_H  0.001f
#define MIN_D  0.001f
#define INV_BN 0.9999950000374997f

// Scratch (__device__ globals: allocation-free rule)
__device__ float g_h1[(size_t)B_ROWS * HDIM];
__device__ float g_h2[(size_t)B_ROWS * HDIM];
__device__ float g_params[(size_t)B_ROWS * DOUT];
__device__ float g_xe [(size_t)B_ROWS * 64];       // packed even cols of x (tf32-rounded)
__device__ float g_w1r[(size_t)64   * HDIM];       // tf32-rounded W1 [64,2048]
__device__ float g_w2r[(size_t)HDIM * HDIM];       // tf32-rounded W2
__device__ float g_w3r[(size_t)HDIM * DOUT];       // tf32-rounded W3

__device__ __forceinline__ float tf32r(float x) {
    uint32_t u;
    asm("cvt.rna.tf32.f32 %0, %1;" : "=r"(u) : "f"(x));
    return __uint_as_float(u);
}

__device__ __forceinline__ void mma_tf32(float* d, const uint32_t* a, const uint32_t* b) {
    asm volatile(
        "mma.sync.aligned.m16n8k8.row.col.f32.tf32.tf32.f32 "
        "{%0,%1,%2,%3}, {%4,%5,%6,%7}, {%8,%9}, {%0,%1,%2,%3};"
        : "+f"(d[0]), "+f"(d[1]), "+f"(d[2]), "+f"(d[3])
        : "r"(a[0]), "r"(a[1]), "r"(a[2]), "r"(a[3]), "r"(b[0]), "r"(b[1]));
}

__device__ __forceinline__ void cp_async16(uint32_t saddr, const void* gptr) {
    asm volatile("cp.async.cg.shared.global [%0], [%1], 16;" :: "r"(saddr), "l"(gptr));
}
#define CP_COMMIT() asm volatile("cp.async.commit_group;" ::: "memory")
#define CP_WAIT1()  asm volatile("cp.async.wait_group 1;" ::: "memory")

// ===========================================================================
// tf32 mma.sync GEMM: C[M x N] = epilogue(A[M x K] @ W[K x N] + bias)
//   Block tile 128 x 256, K-chunk 32, 3-stage cp.async pipeline, 256 threads.
//   8 warps in 2(M) x 4(N); warp tile 64 x 64 = 4x8 m16n8k8 tiles.
//   SMEM: As[128][36] (m-major), Bs[32][264] (k-major).
//     A frag reads: bank = (4g + c) mod 32 -> all 32 distinct, conflict-free.
//     B frag reads: bank = (8c + g + nb) mod 32 -> all 32 distinct, conflict-free.
//   EPI 0: tf32round(gamma*relu(z+bias)*INV_BN + beta)    EPI 1: z + bias
// ===========================================================================
#define A_LD   36
#define B_LD   264
#define A_WORDS (128 * A_LD)              // 4608 words
#define B_WORDS (32 * B_LD)               // 8448 words
#define STAGE_WORDS (A_WORDS + B_WORDS)   // 13056 words
#define SMEM_BYTES  (3 * STAGE_WORDS * 4) // 156672 B

template <int EPI>
__global__ void __launch_bounds__(256, 1) mma_gemm(
    const float* __restrict__ A, int lda,
    const float* __restrict__ W, int ldb,
    float* __restrict__ C, int ldc, int K,
    const float* __restrict__ bias,
    const float* __restrict__ gamma,
    const float* __restrict__ beta)
{
    extern __shared__ float smem[];
    const int tid = threadIdx.x;
    const int wid = tid >> 5;
    const int lane = tid & 31;
    const int g = lane >> 2;           // 0..7
    const int c = lane & 3;            // 0..3
    const int wm = wid >> 2;           // 0..1 -> 64 rows
    const int wn = wid & 3;            // 0..3 -> 64 cols
    const int row0 = blockIdx.y * 128;
    const int col0 = blockIdx.x * 256;
    const int NK = K / 32;

    // cp.async staging assignments
    const int am = tid >> 3;                 // A row 0..31 (x4 -> 128)
    const int akq = (tid & 7) * 4;           // A k quad
    const int bk = tid >> 6;                 // B k 0..3 (x8 -> 32)
    const int bnq = (tid & 63) * 4;          // B n quad 0..252

    uint32_t smem_u32;
    {
        uint64_t t = __cvta_generic_to_shared(smem);
        smem_u32 = (uint32_t)t;
    }

    float acc[4][8][4];
#pragma unroll
    for (int i = 0; i < 4; ++i)
#pragma unroll
        for (int j = 0; j < 8; ++j)
#pragma unroll
            for (int q = 0; q < 4; ++q) acc[i][j][q] = 0.0f;

    auto issue_stage = [&](int s, int kt) {
        const uint32_t abase = smem_u32 + (uint32_t)(s * STAGE_WORDS) * 4u;
        const uint32_t bbase = abase + A_WORDS * 4u;
#pragma unroll
        for (int it = 0; it < 4; ++it) {
            const int m = am + it * 32;
            cp_async16(abase + (uint32_t)(m * A_LD + akq) * 4u,
                       A + (size_t)(row0 + m) * lda + kt + akq);
        }
#pragma unroll
        for (int it = 0; it < 8; ++it) {
            const int k = bk + it * 4;
            cp_async16(bbase + (uint32_t)(k * B_LD + bnq) * 4u,
                       W + (size_t)(kt + k) * ldb + col0 + bnq);
        }
    };

    // prologue: prefetch stages 0,1
#pragma unroll
    for (int j = 0; j < 2; ++j) {
        if (j < NK) issue_stage(j, j * 32);
        CP_COMMIT();
    }

    for (int i = 0; i < NK; ++i) {
        CP_WAIT1();
        __syncthreads();

        if (i + 2 < NK) issue_stage((i + 2) % 3, (i + 2) * 32);
        CP_COMMIT();

        const int s = i % 3;
        const float* As = smem + s * STAGE_WORDS;                 // [128][36]
        const float* Bs = smem + s * STAGE_WORDS + A_WORDS;       // [32][264]

#pragma unroll
        for (int ks = 0; ks < 32; ks += 8) {
            uint32_t af[4][4], bf[8][2];
#pragma unroll
            for (int mt = 0; mt < 4; ++mt) {
                const int rb = wm * 64 + mt * 16;
                af[mt][0] = __float_as_uint(As[(rb + g)     * A_LD + ks + c]);
                af[mt][1] = __float_as_uint(As[(rb + g + 8) * A_LD + ks + c]);
                af[mt][2] = __float_as_uint(As[(rb + g)     * A_LD + ks + c + 4]);
                af[mt][3] = __float_as_uint(As[(rb + g + 8) * A_LD + ks + c + 4]);
            }
#pragma unroll
            for (int nt = 0; nt < 8; ++nt) {
                const int nb = wn * 64 + nt * 8;
                bf[nt][0] = __float_as_uint(Bs[(ks + c)     * B_LD + nb + g]);
                bf[nt][1] = __float_as_uint(Bs[(ks + c + 4) * B_LD + nb + g]);
            }
#pragma unroll
            for (int mt = 0; mt < 4; ++mt)
#pragma unroll
                for (int nt = 0; nt < 8; ++nt)
                    mma_tf32(acc[mt][nt], af[mt], bf[nt]);
        }
        __syncthreads();
    }

    // ---- epilogue ----
#pragma unroll
    for (int mt = 0; mt < 4; ++mt) {
        const int r0 = row0 + wm * 64 + mt * 16 + g;
#pragma unroll
        for (int nt = 0; nt < 8; ++nt) {
            const int cb = col0 + wn * 64 + nt * 8 + 2 * c;
            float z[4];
            z[0] = acc[mt][nt][0] + __ldg(&bias[cb]);
            z[1] = acc[mt][nt][1] + __ldg(&bias[cb + 1]);
            z[2] = acc[mt][nt][2] + __ldg(&bias[cb]);
            z[3] = acc[mt][nt][3] + __ldg(&bias[cb + 1]);
            if (EPI == 0) {
                const float ga0 = __ldg(&gamma[cb]),     be0 = __ldg(&beta[cb]);
                const float ga1 = __ldg(&gamma[cb + 1]), be1v = __ldg(&beta[cb + 1]);
                z[0] = tf32r(ga0 * fmaxf(z[0], 0.0f) * INV_BN + be0);
                z[1] = tf32r(ga1 * fmaxf(z[1], 0.0f) * INV_BN + be1v);
                z[2] = tf32r(ga0 * fmaxf(z[2], 0.0f) * INV_BN + be0);
                z[3] = tf32r(ga1 * fmaxf(z[3], 0.0f) * INV_BN + be1v);
            }
            *(float2*)&C[(size_t)r0 * ldc + cb]       = make_float2(z[0], z[1]);
            *(float2*)&C[(size_t)(r0 + 8) * ldc + cb] = make_float2(z[2], z[3]);
        }
    }
}

// ===========================================================================
// Prep kernels
// ===========================================================================
__global__ void pack_x_kernel(const float* __restrict__ x, float* __restrict__ xe)
{
    const int i = blockIdx.x * 256 + threadIdx.x;   // over B_ROWS*64
    const int row = i >> 6, j = i & 63;
    xe[i] = tf32r(x[(size_t)row * IN_DIM + 2 * j]);
}

__global__ void round_kernel(const float* __restrict__ in, float* __restrict__ out, int n)
{
    const int i = blockIdx.x * 256 + threadIdx.x;
    if (i < n) out[i] = tf32r(in[i]);
}

// ===========================================================================
// RQ-spline + scatter epilogue
// ===========================================================================
__global__ __launch_bounds__(256) void spline_kernel(
    const float* __restrict__ x,
    const float* __restrict__ params,
    float* __restrict__ out,
    float* __restrict__ logdet)
{
    const int tid = threadIdx.x;
    const int row = blockIdx.x * 4 + (tid >> 6);
    const int j = tid & 63;
    const float* p = params + (size_t)row * DOUT + j * 24;

    float wr[NBINS], hr[NBINS], drw[NBINS];
#pragma unroll
    for (int k = 0; k < NBINS; ++k) wr[k] = p[k];
#pragma unroll
    for (int k = 0; k < NBINS; ++k) hr[k] = p[NBINS + k];
#pragma unroll
    for (int k = 0; k < NBINS; ++k) drw[k] = p[2 * NBINS + k];

    const float xi = x[(size_t)row * IN_DIM + 2 * j + 1];
    const float xt = x[(size_t)row * IN_DIM + 2 * j];

    float cw[NBINS + 1], ch[NBINS + 1], dd[NBINS + 1];
    {
        float m = wr[0];
#pragma unroll
        for (int k = 1; k < NBINS; ++k) m = fmaxf(m, wr[k]);
        float e[NBINS], s = 0.0f;
#pragma unroll
        for (int k = 0; k < NBINS; ++k) { e[k] = expf(wr[k] - m); s += e[k]; }
        const float inv = 1.0f / s;
        cw[0] = 0.0f;
#pragma unroll
        for (int k = 0; k < NBINS; ++k)
            cw[k + 1] = cw[k] + (MIN_W + (1.0f - MIN_W * NBINS) * e[k] * inv);
    }
    {
        float m = hr[0];
#pragma unroll
        for (int k = 1; k < NBINS; ++k) m = fmaxf(m, hr[k]);
        float e[NBINS], s = 0.0f;
#pragma unroll
        for (int k = 0; k < NBINS; ++k) { e[k] = expf(hr[k] - m); s += e[k]; }
        const float inv = 1.0f / s;
        ch[0] = 0.0f;
#pragma unroll
        for (int k = 0; k < NBINS; ++k)
            ch[k + 1] = ch[k] + (MIN_H + (1.0f - MIN_H * NBINS) * e[k] * inv);
    }
#pragma unroll
    for (int k = 0; k < NBINS; ++k) {
        const float v = drw[k];
        dd[k] = MIN_D + (fmaxf(v, 0.0f) + log1pf(expf(-fabsf(v))));
    }
    dd[NBINS] = MIN_D;

    int bin = 0;
#pragma unroll
    for (int k = 0; k < NBINS; ++k) bin += (xi > cw[k]) ? 1 : 0;
    bin = min(max(bin, 0), NBINS - 1);

    const float xl = cw[bin], xr = cw[bin + 1];
    const float yl = ch[bin], yr = ch[bin + 1];
    const float bw = xr - xl, bh = yr - yl;
    const float dl = dd[bin], dr = dd[bin + 1];

    float t = (xi - xl) / bw;
    t = fminf(fmaxf(t, 0.0f), 1.0f);

    const float num = bh * (dl * t * t + 2.0f * t * (1.0f - t));
    const float den = dl + (dr - dl) * t;
    const float yv = yl + num / den;
    const float ld = logf(bh) + 2.0f * logf(2.0f * t * (1.0f - t) * dr + dl) - logf(den);

    out[(size_t)row * IN_DIM + 2 * j] = xt;
    out[(size_t)row * IN_DIM + 2 * j + 1] = yv;

    __shared__ float red[256];
    red[tid] = ld;
    __syncthreads();
    for (int s = 32; s > 0; s >>= 1) {
        if ((tid & 63) < s) red[tid] += red[tid + s];
        __syncthreads();
    }
    if ((tid & 63) == 0) logdet[row] = red[tid];
}

// ===========================================================================
// Host side
// ===========================================================================
extern "C" void kernel_launch(void* const* d_in, const int* in_sizes, int n_in,
                              void* d_out, int out_size)
{
    const float* x   = (const float*)d_in[0];
    const float* W1  = (const float*)d_in[1];
    const float* b1  = (const float*)d_in[2];
    const float* g1  = (const float*)d_in[3];
    const float* be1 = (const float*)d_in[4];
    const float* W2  = (const float*)d_in[5];
    const float* b2  = (const float*)d_in[6];
    const float* g2  = (const float*)d_in[7];
    const float* be2 = (const float*)d_in[8];
    const float* W3  = (const float*)d_in[9];
    const float* b3  = (const float*)d_in[10];

    float* out    = (float*)d_out;
    float* logdet = out + (size_t)B_ROWS * IN_DIM;

    float *h1, *h2, *pp, *xe, *w1r, *w2r, *w3r;
    cudaGetSymbolAddress((void**)&h1,  g_h1);
    cudaGetSymbolAddress((void**)&h2,  g_h2);
    cudaGetSymbolAddress((void**)&pp,  g_params);
    cudaGetSymbolAddress((void**)&xe,  g_xe);
    cudaGetSymbolAddress((void**)&w1r, g_w1r);
    cudaGetSymbolAddress((void**)&w2r, g_w2r);
    cudaGetSymbolAddress((void**)&w3r, g_w3r);

    cudaFuncSetAttribute(mma_gemm<0>, cudaFuncAttributeMaxDynamicSharedMemorySize, SMEM_BYTES);
    cudaFuncSetAttribute(mma_gemm<1>, cudaFuncAttributeMaxDynamicSharedMemorySize, SMEM_BYTES);

    // Prep: pack x even cols (tf32) + round weights to tf32 (rna)
    pack_x_kernel<<<(B_ROWS * 64) / 256, 256>>>(x, xe);
    round_kernel<<<(64 * HDIM + 255) / 256, 256>>>(W1, w1r, 64 * HDIM);
    round_kernel<<<(HDIM * HDIM + 255) / 256, 256>>>(W2, w2r, HDIM * HDIM);
    round_kernel<<<(HDIM * DOUT + 255) / 256, 256>>>(W3, w3r, HDIM * DOUT);

    // GEMM1: [32768 x 64] @ [64 x 2048]
    mma_gemm<0><<<dim3(HDIM / 256, B_ROWS / 128), 256, SMEM_BYTES>>>(
        xe, 64, w1r, HDIM, h1, HDIM, 64, b1, g1, be1);
    // GEMM2: [32768 x 2048] @ [2048 x 2048]
    mma_gemm<0><<<dim3(HDIM / 256, B_ROWS / 128), 256, SMEM_BYTES>>>(
        h1, HDIM, w2r, HDIM, h2, HDIM, HDIM, b2, g2, be2);
    // GEMM3: [32768 x 2048] @ [2048 x 1536]
    mma_gemm<1><<<dim3(DOUT / 256, B_ROWS / 128), 256, SMEM_BYTES>>>(
        h2, HDIM, w3r, DOUT, pp, DOUT, HDIM, b3, (const float*)0, (const float*)0);

    // Spline + scatter + log_det
    spline_kernel<<<B_ROWS / 4, 256>>>(x, pp, out, logdet);
}

// round 8
// speedup vs baseline: 8.8465x; 1.8687x over previous
#include <cuda_runtime.h>
#include <cuda_fp16.h>
#include <math.h>
#include <stdint.h>

// ===========================================================================
// Problem constants
// ===========================================================================
#define B_ROWS 32768
#define IN_DIM 128
#define HDIM   2048
#define DOUT   1536
#define NBINS  8
#define MIN_W  0.001f
#define MIN_H  0.001f
#define MIN_D  0.001f
#define INV_BN 0.9999950000374997f

// Scratch (__device__ globals: allocation-free rule)
__device__ __half  g_h1[(size_t)B_ROWS * HDIM];
__device__ __half  g_h2[(size_t)B_ROWS * HDIM];
__device__ float   g_params[(size_t)B_ROWS * DOUT];
__device__ __half  g_xe [(size_t)B_ROWS * 64];          // even cols of x, fp16
__device__ uint32_t g_w1p[(size_t)32   * HDIM];         // W1 k-pair packed [K/2][N]
__device__ uint32_t g_w2p[(size_t)1024 * HDIM];         // W2 packed
__device__ uint32_t g_w3p[(size_t)1024 * DOUT];         // W3 packed

__device__ __forceinline__ void mma_f16(float* d, const uint32_t* a, const uint32_t* b) {
    asm volatile(
        "mma.sync.aligned.m16n8k16.row.col.f32.f16.f16.f32 "
        "{%0,%1,%2,%3}, {%4,%5,%6,%7}, {%8,%9}, {%0,%1,%2,%3};"
        : "+f"(d[0]), "+f"(d[1]), "+f"(d[2]), "+f"(d[3])
        : "r"(a[0]), "r"(a[1]), "r"(a[2]), "r"(a[3]), "r"(b[0]), "r"(b[1]));
}

__device__ __forceinline__ void cp_async16(uint32_t saddr, const void* gptr) {
    asm volatile("cp.async.cg.shared.global [%0], [%1], 16;" :: "r"(saddr), "l"(gptr));
}
#define CP_COMMIT() asm volatile("cp.async.commit_group;" ::: "memory")
#define CP_WAIT1()  asm volatile("cp.async.wait_group 1;" ::: "memory")

// ===========================================================================
// fp16 mma.sync GEMM: C[M x N] = epilogue(A[M x K] @ W[K x N] + bias)
//   Block tile 128 x 256, K-chunk 64, 3-stage cp.async, 256 threads.
//   8 warps 2(M) x 4(N); warp tile 64 x 64 = 4x8 m16n8k16 tiles.
//   SMEM (32-bit words): Asw[128][36]  (m-major, k-pairs; pad 4 words)
//                        Bsw[32][264]  (kpair-major, packed {W[2k],W[2k+1]})
//   A frag word bank = (36g + c) mod 32 = (4g + c) -> 32 distinct, conflict-free.
//   B frag word bank = (264c + g + nb) mod 32 = (8c + g) -> conflict-free.
//   EPI 0: half( gamma*relu(z+bias)*INV_BN + beta )   -> __half C
//   EPI 1: z + bias                                   -> float C
// ===========================================================================
#define A_LDW  36
#define B_LDW  264
#define A_WORDS (128 * A_LDW)              // 4608
#define B_WORDS (32 * B_LDW)               // 8448
#define STAGE_WORDS (A_WORDS + B_WORDS)    // 13056
#define SMEM_BYTES  (3 * STAGE_WORDS * 4)  // 156672 B

template <int EPI>
__global__ void __launch_bounds__(256, 1) mma_gemm_h(
    const __half* __restrict__ A, int lda,          // lda in halves
    const uint32_t* __restrict__ Wp, int ldbw,      // packed words per row
    void* __restrict__ Cv, int ldc, int K,
    const float* __restrict__ bias,
    const float* __restrict__ gamma,
    const float* __restrict__ beta)
{
    extern __shared__ uint32_t smw[];
    const int tid = threadIdx.x;
    const int wid = tid >> 5;
    const int lane = tid & 31;
    const int g = lane >> 2;           // 0..7
    const int c = lane & 3;            // 0..3
    const int wm = wid >> 2;           // 0..1 -> 64 rows
    const int wn = wid & 3;            // 0..3 -> 64 cols
    const int row0 = blockIdx.y * 128;
    const int col0 = blockIdx.x * 256;
    const int NK = K / 64;

    // cp.async staging
    const int am  = tid >> 3;          // A row 0..31 (x4 -> 128)
    const int akc = (tid & 7) * 4;     // A word-chunk (4 words = 16B = 8 halves)
    const int bkp = tid >> 6;          // B kpair-row 0..3 (x8 -> 32)
    const int bnc = (tid & 63) * 4;    // B word-chunk

    uint32_t smem_u32;
    {
        uint64_t t = __cvta_generic_to_shared(smw);
        smem_u32 = (uint32_t)t;
    }

    float acc[4][8][4];
#pragma unroll
    for (int i = 0; i < 4; ++i)
#pragma unroll
        for (int j = 0; j < 8; ++j)
#pragma unroll
            for (int q = 0; q < 4; ++q) acc[i][j][q] = 0.0f;

    auto issue_stage = [&](int s, int kt) {            // kt in k-halves
        const uint32_t abase = smem_u32 + (uint32_t)(s * STAGE_WORDS) * 4u;
        const uint32_t bbase = abase + A_WORDS * 4u;
#pragma unroll
        for (int it = 0; it < 4; ++it) {
            const int m = am + it * 32;
            cp_async16(abase + (uint32_t)(m * A_LDW + akc) * 4u,
                       A + (size_t)(row0 + m) * lda + kt + akc * 2);
        }
#pragma unroll
        for (int it = 0; it < 8; ++it) {
            const int kp = bkp + it * 4;
            cp_async16(bbase + (uint32_t)(kp * B_LDW + bnc) * 4u,
                       Wp + (size_t)(kt / 2 + kp) * ldbw + col0 + bnc);
        }
    };

    // prologue: prefetch stages 0,1
#pragma unroll
    for (int j = 0; j < 2; ++j) {
        if (j < NK) issue_stage(j, j * 64);
        CP_COMMIT();
    }

    for (int i = 0; i < NK; ++i) {
        CP_WAIT1();
        __syncthreads();

        if (i + 2 < NK) issue_stage((i + 2) % 3, (i + 2) * 64);
        CP_COMMIT();

        const int s = i % 3;
        const uint32_t* Asw = smw + s * STAGE_WORDS;           // [128][36] words
        const uint32_t* Bsw = Asw + A_WORDS;                   // [32][264] words

#pragma unroll
        for (int ksw = 0; ksw < 32; ksw += 8) {                // 4 ksteps of k16
            uint32_t af[4][4], bf[8][2];
#pragma unroll
            for (int mt = 0; mt < 4; ++mt) {
                const int rb = wm * 64 + mt * 16;
                af[mt][0] = Asw[(rb + g)     * A_LDW + ksw + c];
                af[mt][1] = Asw[(rb + g + 8) * A_LDW + ksw + c];
                af[mt][2] = Asw[(rb + g)     * A_LDW + ksw + c + 4];
                af[mt][3] = Asw[(rb + g + 8) * A_LDW + ksw + c + 4];
            }
#pragma unroll
            for (int nt = 0; nt < 8; ++nt) {
                const int nb = wn * 64 + nt * 8;
                bf[nt][0] = Bsw[(ksw + c)     * B_LDW + nb + g];
                bf[nt][1] = Bsw[(ksw + c + 4) * B_LDW + nb + g];
            }
#pragma unroll
            for (int mt = 0; mt < 4; ++mt)
#pragma unroll
                for (int nt = 0; nt < 8; ++nt)
                    mma_f16(acc[mt][nt], af[mt], bf[nt]);
        }
        __syncthreads();
    }

    // ---- epilogue ----
#pragma unroll
    for (int mt = 0; mt < 4; ++mt) {
        const int r0 = row0 + wm * 64 + mt * 16 + g;
#pragma unroll
        for (int nt = 0; nt < 8; ++nt) {
            const int cb = col0 + wn * 64 + nt * 8 + 2 * c;
            float z[4];
            z[0] = acc[mt][nt][0] + __ldg(&bias[cb]);
            z[1] = acc[mt][nt][1] + __ldg(&bias[cb + 1]);
            z[2] = acc[mt][nt][2] + __ldg(&bias[cb]);
            z[3] = acc[mt][nt][3] + __ldg(&bias[cb + 1]);
            if (EPI == 0) {
                const float ga0 = __ldg(&gamma[cb]),     be0  = __ldg(&beta[cb]);
                const float ga1 = __ldg(&gamma[cb + 1]), be1v = __ldg(&beta[cb + 1]);
                z[0] = ga0 * fmaxf(z[0], 0.0f) * INV_BN + be0;
                z[1] = ga1 * fmaxf(z[1], 0.0f) * INV_BN + be1v;
                z[2] = ga0 * fmaxf(z[2], 0.0f) * INV_BN + be0;
                z[3] = ga1 * fmaxf(z[3], 0.0f) * INV_BN + be1v;
                __half* C = (__half*)Cv;
                *(__half2*)&C[(size_t)r0 * ldc + cb]       = __floats2half2_rn(z[0], z[1]);
                *(__half2*)&C[(size_t)(r0 + 8) * ldc + cb] = __floats2half2_rn(z[2], z[3]);
            } else {
                float* C = (float*)Cv;
                *(float2*)&C[(size_t)r0 * ldc + cb]       = make_float2(z[0], z[1]);
                *(float2*)&C[(size_t)(r0 + 8) * ldc + cb] = make_float2(z[2], z[3]);
            }
        }
    }
}

// ===========================================================================
// Prep kernels
// ===========================================================================
__global__ void pack_x_kernel(const float* __restrict__ x, __half* __restrict__ xe)
{
    const int i = blockIdx.x * 256 + threadIdx.x;   // over B_ROWS*64
    const int row = i >> 6, j = i & 63;
    xe[i] = __float2half_rn(x[(size_t)row * IN_DIM + 2 * j]);
}

// pack W[K][N] fp32 -> [K/2][N] uint32 words {h(W[2kp][n]), h(W[2kp+1][n])}
__global__ void pack_w_kernel(const float* __restrict__ W, uint32_t* __restrict__ out,
                              int K2, int N)
{
    const int i = blockIdx.x * 256 + threadIdx.x;
    if (i >= K2 * N) return;
    const int kp = i / N, n = i - kp * N;
    const __half lo = __float2half_rn(W[(size_t)(2 * kp) * N + n]);
    const __half hi = __float2half_rn(W[(size_t)(2 * kp + 1) * N + n]);
    out[i] = (uint32_t)__half_as_ushort(lo) | ((uint32_t)__half_as_ushort(hi) << 16);
}

// ===========================================================================
// RQ-spline + scatter epilogue
// ===========================================================================
__global__ __launch_bounds__(256) void spline_kernel(
    const float* __restrict__ x,
    const float* __restrict__ params,
    float* __restrict__ out,
    float* __restrict__ logdet)
{
    const int tid = threadIdx.x;
    const int row = blockIdx.x * 4 + (tid >> 6);
    const int j = tid & 63;
    const float* p = params + (size_t)row * DOUT + j * 24;

    float wr[NBINS], hr[NBINS], drw[NBINS];
#pragma unroll
    for (int k = 0; k < NBINS; ++k) wr[k] = p[k];
#pragma unroll
    for (int k = 0; k < NBINS; ++k) hr[k] = p[NBINS + k];
#pragma unroll
    for (int k = 0; k < NBINS; ++k) drw[k] = p[2 * NBINS + k];

    const float xi = x[(size_t)row * IN_DIM + 2 * j + 1];
    const float xt = x[(size_t)row * IN_DIM + 2 * j];

    float cw[NBINS + 1], ch[NBINS + 1], dd[NBINS + 1];
    {
        float m = wr[0];
#pragma unroll
        for (int k = 1; k < NBINS; ++k) m = fmaxf(m, wr[k]);
        float e[NBINS], s = 0.0f;
#pragma unroll
        for (int k = 0; k < NBINS; ++k) { e[k] = expf(wr[k] - m); s += e[k]; }
        const float inv = 1.0f / s;
        cw[0] = 0.0f;
#pragma unroll
        for (int k = 0; k < NBINS; ++k)
            cw[k + 1] = cw[k] + (MIN_W + (1.0f - MIN_W * NBINS) * e[k] * inv);
    }
    {
        float m = hr[0];
#pragma unroll
        for (int k = 1; k < NBINS; ++k) m = fmaxf(m, hr[k]);
        float e[NBINS], s = 0.0f;
#pragma unroll
        for (int k = 0; k < NBINS; ++k) { e[k] = expf(hr[k] - m); s += e[k]; }
        const float inv = 1.0f / s;
        ch[0] = 0.0f;
#pragma unroll
        for (int k = 0; k < NBINS; ++k)
            ch[k + 1] = ch[k] + (MIN_H + (1.0f - MIN_H * NBINS) * e[k] * inv);
    }
#pragma unroll
    for (int k = 0; k < NBINS; ++k) {
        const float v = drw[k];
        dd[k] = MIN_D + (fmaxf(v, 0.0f) + log1pf(expf(-fabsf(v))));
    }
    dd[NBINS] = MIN_D;

    int bin = 0;
#pragma unroll
    for (int k = 0; k < NBINS; ++k) bin += (xi > cw[k]) ? 1 : 0;
    bin = min(max(bin, 0), NBINS - 1);

    const float xl = cw[bin], xr = cw[bin + 1];
    const float yl = ch[bin], yr = ch[bin + 1];
    const float bw = xr - xl, bh = yr - yl;
    const float dl = dd[bin], dr = dd[bin + 1];

    float t = (xi - xl) / bw;
    t = fminf(fmaxf(t, 0.0f), 1.0f);

    const float num = bh * (dl * t * t + 2.0f * t * (1.0f - t));
    const float den = dl + (dr - dl) * t;
    const float yv = yl + num / den;
    const float ld = logf(bh) + 2.0f * logf(2.0f * t * (1.0f - t) * dr + dl) - logf(den);

    out[(size_t)row * IN_DIM + 2 * j] = xt;
    out[(size_t)row * IN_DIM + 2 * j + 1] = yv;

    __shared__ float red[256];
    red[tid] = ld;
    __syncthreads();
    for (int s = 32; s > 0; s >>= 1) {
        if ((tid & 63) < s) red[tid] += red[tid + s];
        __syncthreads();
    }
    if ((tid & 63) == 0) logdet[row] = red[tid];
}

// ===========================================================================
// Host side
// ===========================================================================
extern "C" void kernel_launch(void* const* d_in, const int* in_sizes, int n_in,
                              void* d_out, int out_size)
{
    const float* x   = (const float*)d_in[0];
    const float* W1  = (const float*)d_in[1];
    const float* b1  = (const float*)d_in[2];
    const float* g1  = (const float*)d_in[3];
    const float* be1 = (const float*)d_in[4];
    const float* W2  = (const float*)d_in[5];
    const float* b2  = (const float*)d_in[6];
    const float* g2  = (const float*)d_in[7];
    const float* be2 = (const float*)d_in[8];
    const float* W3  = (const float*)d_in[9];
    const float* b3  = (const float*)d_in[10];

    float* out    = (float*)d_out;
    float* logdet = out + (size_t)B_ROWS * IN_DIM;

    __half *h1, *h2, *xe;
    float *pp;
    uint32_t *w1p, *w2p, *w3p;
    cudaGetSymbolAddress((void**)&h1,  g_h1);
    cudaGetSymbolAddress((void**)&h2,  g_h2);
    cudaGetSymbolAddress((void**)&pp,  g_params);
    cudaGetSymbolAddress((void**)&xe,  g_xe);
    cudaGetSymbolAddress((void**)&w1p, g_w1p);
    cudaGetSymbolAddress((void**)&w2p, g_w2p);
    cudaGetSymbolAddress((void**)&w3p, g_w3p);

    cudaFuncSetAttribute(mma_gemm_h<0>, cudaFuncAttributeMaxDynamicSharedMemorySize, SMEM_BYTES);
    cudaFuncSetAttribute(mma_gemm_h<1>, cudaFuncAttributeMaxDynamicSharedMemorySize, SMEM_BYTES);

    // Prep: pack x even cols + k-pair-interleave weights (all fp16)
    pack_x_kernel<<<(B_ROWS * 64) / 256, 256>>>(x, xe);
    pack_w_kernel<<<(32   * HDIM + 255) / 256, 256>>>(W1, w1p, 32,   HDIM);
    pack_w_kernel<<<(1024 * HDIM + 255) / 256, 256>>>(W2, w2p, 1024, HDIM);
    pack_w_kernel<<<(1024 * DOUT + 255) / 256, 256>>>(W3, w3p, 1024, DOUT);

    // GEMM1: [32768 x 64] @ [64 x 2048] -> h1 (fp16)
    mma_gemm_h<0><<<dim3(HDIM / 256, B_ROWS / 128), 256, SMEM_BYTES>>>(
        xe, 64, w1p, HDIM, h1, HDIM, 64, b1, g1, be1);
    // GEMM2: [32768 x 2048] @ [2048 x 2048] -> h2 (fp16)
    mma_gemm_h<0><<<dim3(HDIM / 256, B_ROWS / 128), 256, SMEM_BYTES>>>(
        h1, HDIM, w2p, HDIM, h2, HDIM, HDIM, b2, g2, be2);
    // GEMM3: [32768 x 2048] @ [2048 x 1536] -> params (fp32)
    mma_gemm_h<1><<<dim3(DOUT / 256, B_ROWS / 128), 256, SMEM_BYTES>>>(
        h2, HDIM, w3p, DOUT, pp, DOUT, HDIM, b3, (const float*)0, (const float*)0);

    // Spline + scatter + log_det
    spline_kernel<<<B_ROWS / 4, 256>>>(x, pp, out, logdet);
}

// round 9
// speedup vs baseline: 8.8582x; 1.0013x over previous
#include <cuda_runtime.h>
#include <cuda_fp16.h>
#include <math.h>
#include <stdint.h>

// ===========================================================================
// Problem constants
// ===========================================================================
#define B_ROWS 32768
#define IN_DIM 128
#define HDIM   2048
#define DOUT   1536
#define NBINS  8
#define MIN_W  0.001f
#define MIN_H  0.001f
#define MIN_D  0.001f
#define INV_BN 0.9999950000374997f

// Scratch (__device__ globals: allocation-free rule)
__device__ __half  g_h1[(size_t)B_ROWS * HDIM];
__device__ __half  g_h2[(size_t)B_ROWS * HDIM];
__device__ float   g_params[(size_t)B_ROWS * DOUT];
__device__ __half  g_xe [(size_t)B_ROWS * 64];          // even cols of x, fp16
__device__ uint32_t g_w1p[(size_t)32   * HDIM];         // W1 k-pair packed [K/2][N]
__device__ uint32_t g_w2p[(size_t)1024 * HDIM];         // W2 packed
__device__ uint32_t g_w3p[(size_t)1024 * DOUT];         // W3 packed

__device__ __forceinline__ void mma_f16(float* d, const uint32_t* a, const uint32_t* b) {
    asm volatile(
        "mma.sync.aligned.m16n8k16.row.col.f32.f16.f16.f32 "
        "{%0,%1,%2,%3}, {%4,%5,%6,%7}, {%8,%9}, {%0,%1,%2,%3};"
        : "+f"(d[0]), "+f"(d[1]), "+f"(d[2]), "+f"(d[3])
        : "r"(a[0]), "r"(a[1]), "r"(a[2]), "r"(a[3]), "r"(b[0]), "r"(b[1]));
}

__device__ __forceinline__ void ldmatrix_x4(uint32_t* r, uint32_t saddr) {
    asm volatile("ldmatrix.sync.aligned.m8n8.x4.shared.b16 {%0,%1,%2,%3}, [%4];"
        : "=r"(r[0]), "=r"(r[1]), "=r"(r[2]), "=r"(r[3]) : "r"(saddr));
}

__device__ __forceinline__ void cp_async16(uint32_t saddr, const void* gptr) {
    asm volatile("cp.async.cg.shared.global [%0], [%1], 16;" :: "r"(saddr), "l"(gptr));
}
#define CP_COMMIT() asm volatile("cp.async.commit_group;" ::: "memory")
#define CP_WAIT2()  asm volatile("cp.async.wait_group 2;" ::: "memory")

// ===========================================================================
// fp16 mma.sync GEMM: C[M x N] = epilogue(A[M x K] @ W[K x N] + bias)
//   Block tile 128 x 256, K-chunk 64, 4-stage cp.async, 256 threads.
//   8 warps 2(M) x 4(N); warp tile 64 x 64 = 4x8 m16n8k16 tiles.
//   SMEM (32-bit words): Asw[128][36]  (m-major, k-pair words; pad 4)
//                        Bsw[32][264]  (kpair-major, packed {W[2k],W[2k+1]})
//   A frags via ldmatrix.x4 (rows stride 36 words -> conflict-free phases).
//   B frag word bank = (8c + g) -> conflict-free.
//   EPI 0: half( gamma*relu(z+bias)*INV_BN + beta )   -> __half C
//   EPI 1: z + bias                                   -> float C
// ===========================================================================
#define A_LDW  36
#define B_LDW  264
#define A_WORDS (128 * A_LDW)              // 4608
#define B_WORDS (32 * B_LDW)               // 8448
#define STAGE_WORDS (A_WORDS + B_WORDS)    // 13056
#define N_STAGES 4
#define SMEM_BYTES  (N_STAGES * STAGE_WORDS * 4)  // 208896 B

template <int EPI>
__global__ void __launch_bounds__(256, 1) mma_gemm_h(
    const __half* __restrict__ A, int lda,          // lda in halves
    const uint32_t* __restrict__ Wp, int ldbw,      // packed words per row
    void* __restrict__ Cv, int ldc, int K,
    const float* __restrict__ bias,
    const float* __restrict__ gamma,
    const float* __restrict__ beta)
{
    extern __shared__ uint32_t smw[];
    const int tid = threadIdx.x;
    const int wid = tid >> 5;
    const int lane = tid & 31;
    const int g = lane >> 2;           // 0..7
    const int c = lane & 3;            // 0..3
    const int wm = wid >> 2;           // 0..1 -> 64 rows
    const int wn = wid & 3;            // 0..3 -> 64 cols
    const int row0 = blockIdx.y * 128;
    const int col0 = blockIdx.x * 256;
    const int NK = K / 64;

    // cp.async staging
    const int am  = tid >> 3;          // A row 0..31 (x4 -> 128)
    const int akc = (tid & 7) * 4;     // A word-chunk (4 words = 16B = 8 halves)
    const int bkp = tid >> 6;          // B kpair-row 0..3 (x8 -> 32)
    const int bnc = (tid & 63) * 4;    // B word-chunk

    // ldmatrix lane mapping: q = lane/8 (matrix id), r = lane%8 (row in matrix)
    //   m0: row rb+r,   words +0..3 ; m1: row rb+8+r, words +0..3
    //   m2: row rb+r,   words +4..7 ; m3: row rb+8+r, words +4..7
    const int lq = lane >> 3, lr = lane & 7;
    const int lm_off = ((lq & 1) * 8 + lr) * A_LDW + (lq >> 1) * 4;  // word offset

    uint32_t smem_u32;
    {
        uint64_t t = __cvta_generic_to_shared(smw);
        smem_u32 = (uint32_t)t;
    }

    float acc[4][8][4];
#pragma unroll
    for (int i = 0; i < 4; ++i)
#pragma unroll
        for (int j = 0; j < 8; ++j)
#pragma unroll
            for (int q = 0; q < 4; ++q) acc[i][j][q] = 0.0f;

    auto issue_stage = [&](int s, int kt) {            // kt in k-halves
        const uint32_t abase = smem_u32 + (uint32_t)(s * STAGE_WORDS) * 4u;
        const uint32_t bbase = abase + A_WORDS * 4u;
#pragma unroll
        for (int it = 0; it < 4; ++it) {
            const int m = am + it * 32;
            cp_async16(abase + (uint32_t)(m * A_LDW + akc) * 4u,
                       A + (size_t)(row0 + m) * lda + kt + akc * 2);
        }
#pragma unroll
        for (int it = 0; it < 8; ++it) {
            const int kp = bkp + it * 4;
            cp_async16(bbase + (uint32_t)(kp * B_LDW + bnc) * 4u,
                       Wp + (size_t)(kt / 2 + kp) * ldbw + col0 + bnc);
        }
    };

    // prologue: prefetch stages 0,1,2 (always commit for group accounting)
#pragma unroll
    for (int j = 0; j < N_STAGES - 1; ++j) {
        if (j < NK) issue_stage(j, j * 64);
        CP_COMMIT();
    }

    for (int i = 0; i < NK; ++i) {
        CP_WAIT2();
        __syncthreads();

        if (i + N_STAGES - 1 < NK)
            issue_stage((i + N_STAGES - 1) % N_STAGES, (i + N_STAGES - 1) * 64);
        CP_COMMIT();

        const int s = i % N_STAGES;
        const uint32_t a_stage = smem_u32 + (uint32_t)(s * STAGE_WORDS) * 4u;
        const uint32_t* Bsw = smw + s * STAGE_WORDS + A_WORDS;   // [32][264] words

#pragma unroll
        for (int ksw = 0; ksw < 32; ksw += 8) {                  // 4 ksteps of k16
            uint32_t af[4][4], bf[8][2];
#pragma unroll
            for (int mt = 0; mt < 4; ++mt) {
                const int rb = wm * 64 + mt * 16;
                ldmatrix_x4(af[mt],
                            a_stage + (uint32_t)(rb * A_LDW + ksw + lm_off) * 4u);
            }
#pragma unroll
            for (int nt = 0; nt < 8; ++nt) {
                const int nb = wn * 64 + nt * 8;
                bf[nt][0] = Bsw[(ksw + c)     * B_LDW + nb + g];
                bf[nt][1] = Bsw[(ksw + c + 4) * B_LDW + nb + g];
            }
#pragma unroll
            for (int mt = 0; mt < 4; ++mt)
#pragma unroll
                for (int nt = 0; nt < 8; ++nt)
                    mma_f16(acc[mt][nt], af[mt], bf[nt]);
        }
        __syncthreads();
    }

    // ---- epilogue ----
#pragma unroll
    for (int mt = 0; mt < 4; ++mt) {
        const int r0 = row0 + wm * 64 + mt * 16 + g;
#pragma unroll
        for (int nt = 0; nt < 8; ++nt) {
            const int cb = col0 + wn * 64 + nt * 8 + 2 * c;
            float z[4];
            z[0] = acc[mt][nt][0] + __ldg(&bias[cb]);
            z[1] = acc[mt][nt][1] + __ldg(&bias[cb + 1]);
            z[2] = acc[mt][nt][2] + __ldg(&bias[cb]);
            z[3] = acc[mt][nt][3] + __ldg(&bias[cb + 1]);
            if (EPI == 0) {
                const float ga0 = __ldg(&gamma[cb]),     be0  = __ldg(&beta[cb]);
                const float ga1 = __ldg(&gamma[cb + 1]), be1v = __ldg(&beta[cb + 1]);
                z[0] = ga0 * fmaxf(z[0], 0.0f) * INV_BN + be0;
                z[1] = ga1 * fmaxf(z[1], 0.0f) * INV_BN + be1v;
                z[2] = ga0 * fmaxf(z[2], 0.0f) * INV_BN + be0;
                z[3] = ga1 * fmaxf(z[3], 0.0f) * INV_BN + be1v;
                __half* C = (__half*)Cv;
                *(__half2*)&C[(size_t)r0 * ldc + cb]       = __floats2half2_rn(z[0], z[1]);
                *(__half2*)&C[(size_t)(r0 + 8) * ldc + cb] = __floats2half2_rn(z[2], z[3]);
            } else {
                float* C = (float*)Cv;
                *(float2*)&C[(size_t)r0 * ldc + cb]       = make_float2(z[0], z[1]);
                *(float2*)&C[(size_t)(r0 + 8) * ldc + cb] = make_float2(z[2], z[3]);
            }
        }
    }
}

// ===========================================================================
// Prep kernels
// ===========================================================================
__global__ void pack_x_kernel(const float* __restrict__ x, __half* __restrict__ xe)
{
    const int i = blockIdx.x * 256 + threadIdx.x;   // over B_ROWS*64
    const int row = i >> 6, j = i & 63;
    xe[i] = __float2half_rn(x[(size_t)row * IN_DIM + 2 * j]);
}

// pack W[K][N] fp32 -> [K/2][N] uint32 words {h(W[2kp][n]), h(W[2kp+1][n])}
__global__ void pack_w_kernel(const float* __restrict__ W, uint32_t* __restrict__ out,
                              int K2, int N)
{
    const int i = blockIdx.x * 256 + threadIdx.x;
    if (i >= K2 * N) return;
    const int kp = i / N, n = i - kp * N;
    const __half lo = __float2half_rn(W[(size_t)(2 * kp) * N + n]);
    const __half hi = __float2half_rn(W[(size_t)(2 * kp + 1) * N + n]);
    out[i] = (uint32_t)__half_as_ushort(lo) | ((uint32_t)__half_as_ushort(hi) << 16);
}

// ===========================================================================
// RQ-spline + scatter epilogue
// ===========================================================================
__global__ __launch_bounds__(256) void spline_kernel(
    const float* __restrict__ x,
    const float* __restrict__ params,
    float* __restrict__ out,
    float* __restrict__ logdet)
{
    const int tid = threadIdx.x;
    const int row = blockIdx.x * 4 + (tid >> 6);
    const int j = tid & 63;
    const float* p = params + (size_t)row * DOUT + j * 24;

    float wr[NBINS], hr[NBINS], drw[NBINS];
#pragma unroll
    for (int k = 0; k < NBINS; ++k) wr[k] = p[k];
#pragma unroll
    for (int k = 0; k < NBINS; ++k) hr[k] = p[NBINS + k];
#pragma unroll
    for (int k = 0; k < NBINS; ++k) drw[k] = p[2 * NBINS + k];

    const float xi = x[(size_t)row * IN_DIM + 2 * j + 1];
    const float xt = x[(size_t)row * IN_DIM + 2 * j];

    float cw[NBINS + 1], ch[NBINS + 1], dd[NBINS + 1];
    {
        float m = wr[0];
#pragma unroll
        for (int k = 1; k < NBINS; ++k) m = fmaxf(m, wr[k]);
        float e[NBINS], s = 0.0f;
#pragma unroll
        for (int k = 0; k < NBINS; ++k) { e[k] = expf(wr[k] - m); s += e[k]; }
        const float inv = 1.0f / s;
        cw[0] = 0.0f;
#pragma unroll
        for (int k = 0; k < NBINS; ++k)
            cw[k + 1] = cw[k] + (MIN_W + (1.0f - MIN_W * NBINS) * e[k] * inv);
    }
    {
        float m = hr[0];
#pragma unroll
        for (int k = 1; k < NBINS; ++k) m = fmaxf(m, hr[k]);
        float e[NBINS], s = 0.0f;
#pragma unroll
        for (int k = 0; k < NBINS; ++k) { e[k] = expf(hr[k] - m); s += e[k]; }
        const float inv = 1.0f / s;
        ch[0] = 0.0f;
#pragma unroll
        for (int k = 0; k < NBINS; ++k)
            ch[k + 1] = ch[k] + (MIN_H + (1.0f - MIN_H * NBINS) * e[k] * inv);
    }
#pragma unroll
    for (int k = 0; k < NBINS; ++k) {
        const float v = drw[k];
        dd[k] = MIN_D + (fmaxf(v, 0.0f) + log1pf(expf(-fabsf(v))));
    }
    dd[NBINS] = MIN_D;

    int bin = 0;
#pragma unroll
    for (int k = 0; k < NBINS; ++k) bin += (xi > cw[k]) ? 1 : 0;
    bin = min(max(bin, 0), NBINS - 1);

    const float xl = cw[bin], xr = cw[bin + 1];
    const float yl = ch[bin], yr = ch[bin + 1];
    const float bw = xr - xl, bh = yr - yl;
    const float dl = dd[bin], dr = dd[bin + 1];

    float t = (xi - xl) / bw;
    t = fminf(fmaxf(t, 0.0f), 1.0f);

    const float num = bh * (dl * t * t + 2.0f * t * (1.0f - t));
    const float den = dl + (dr - dl) * t;
    const float yv = yl + num / den;
    const float ld = logf(bh) + 2.0f * logf(2.0f * t * (1.0f - t) * dr + dl) - logf(den);

    out[(size_t)row * IN_DIM + 2 * j] = xt;
    out[(size_t)row * IN_DIM + 2 * j + 1] = yv;

    __shared__ float red[256];
    red[tid] = ld;
    __syncthreads();
    for (int s = 32; s > 0; s >>= 1) {
        if ((tid & 63) < s) red[tid] += red[tid + s];
        __syncthreads();
    }
    if ((tid & 63) == 0) logdet[row] = red[tid];
}

// ===========================================================================
// Host side
// ===========================================================================
extern "C" void kernel_launch(void* const* d_in, const int* in_sizes, int n_in,
                              void* d_out, int out_size)
{
    const float* x   = (const float*)d_in[0];
    const float* W1  = (const float*)d_in[1];
    const float* b1  = (const float*)d_in[2];
    const float* g1  = (const float*)d_in[3];
    const float* be1 = (const float*)d_in[4];
    const float* W2  = (const float*)d_in[5];
    const float* b2  = (const float*)d_in[6];
    const float* g2  = (const float*)d_in[7];
    const float* be2 = (const float*)d_in[8];
    const float* W3  = (const float*)d_in[9];
    const float* b3  = (const float*)d_in[10];

    float* out    = (float*)d_out;
    float* logdet = out + (size_t)B_ROWS * IN_DIM;

    __half *h1, *h2, *xe;
    float *pp;
    uint32_t *w1p, *w2p, *w3p;
    cudaGetSymbolAddress((void**)&h1,  g_h1);
    cudaGetSymbolAddress((void**)&h2,  g_h2);
    cudaGetSymbolAddress((void**)&pp,  g_params);
    cudaGetSymbolAddress((void**)&xe,  g_xe);
    cudaGetSymbolAddress((void**)&w1p, g_w1p);
    cudaGetSymbolAddress((void**)&w2p, g_w2p);
    cudaGetSymbolAddress((void**)&w3p, g_w3p);

    cudaFuncSetAttribute(mma_gemm_h<0>, cudaFuncAttributeMaxDynamicSharedMemorySize, SMEM_BYTES);
    cudaFuncSetAttribute(mma_gemm_h<1>, cudaFuncAttributeMaxDynamicSharedMemorySize, SMEM_BYTES);

    // Prep: pack x even cols + k-pair-interleave weights (all fp16)
    pack_x_kernel<<<(B_ROWS * 64) / 256, 256>>>(x, xe);
    pack_w_kernel<<<(32   * HDIM + 255) / 256, 256>>>(W1, w1p, 32,   HDIM);
    pack_w_kernel<<<(1024 * HDIM + 255) / 256, 256>>>(W2, w2p, 1024, HDIM);
    pack_w_kernel<<<(1024 * DOUT + 255) / 256, 256>>>(W3, w3p, 1024, DOUT);

    // GEMM1: [32768 x 64] @ [64 x 2048] -> h1 (fp16)
    mma_gemm_h<0><<<dim3(HDIM / 256, B_ROWS / 128), 256, SMEM_BYTES>>>(
        xe, 64, w1p, HDIM, h1, HDIM, 64, b1, g1, be1);
    // GEMM2: [32768 x 2048] @ [2048 x 2048] -> h2 (fp16)
    mma_gemm_h<0><<<dim3(HDIM / 256, B_ROWS / 128), 256, SMEM_BYTES>>>(
        h1, HDIM, w2p, HDIM, h2, HDIM, HDIM, b2, g2, be2);
    // GEMM3: [32768 x 2048] @ [2048 x 1536] -> params (fp32)
    mma_gemm_h<1><<<dim3(DOUT / 256, B_ROWS / 128), 256, SMEM_BYTES>>>(
        h2, HDIM, w3p, DOUT, pp, DOUT, HDIM, b3, (const float*)0, (const float*)0);

    // Spline + scatter + log_det
    spline_kernel<<<B_ROWS / 4, 256>>>(x, pp, out, logdet);
}

// round 10
// speedup vs baseline: 9.7165x; 1.0969x over previous
#include <cuda_runtime.h>
#include <cuda_fp16.h>
#include <math.h>
#include <stdint.h>

// ===========================================================================
// Problem constants
// ===========================================================================
#define B_ROWS 32768
#define IN_DIM 128
#define HDIM   2048
#define DOUT   1536
#define NBINS  8
#define MIN_W  0.001f
#define MIN_H  0.001f
#define MIN_D  0.001f
#define INV_BN 0.9999950000374997f

// Scratch (__device__ globals: allocation-free rule)
__device__ __half  g_h1[(size_t)B_ROWS * HDIM];
__device__ __half  g_h2[(size_t)B_ROWS * HDIM];
__device__ float   g_params[(size_t)B_ROWS * DOUT];
__device__ __half  g_xe [(size_t)B_ROWS * 64];          // even cols of x, fp16
__device__ uint32_t g_w1p[(size_t)32   * HDIM];         // W1 k-pair packed [K/2][N]
__device__ uint32_t g_w2p[(size_t)1024 * HDIM];         // W2 packed
__device__ uint32_t g_w3p[(size_t)1024 * DOUT];         // W3 packed

__device__ __forceinline__ void mma_f16(float* d, const uint32_t* a, const uint32_t* b) {
    asm volatile(
        "mma.sync.aligned.m16n8k16.row.col.f32.f16.f16.f32 "
        "{%0,%1,%2,%3}, {%4,%5,%6,%7}, {%8,%9}, {%0,%1,%2,%3};"
        : "+f"(d[0]), "+f"(d[1]), "+f"(d[2]), "+f"(d[3])
        : "r"(a[0]), "r"(a[1]), "r"(a[2]), "r"(a[3]), "r"(b[0]), "r"(b[1]));
}

__device__ __forceinline__ void ldmatrix_x4(uint32_t* r, uint32_t saddr) {
    asm volatile("ldmatrix.sync.aligned.m8n8.x4.shared.b16 {%0,%1,%2,%3}, [%4];"
        : "=r"(r[0]), "=r"(r[1]), "=r"(r[2]), "=r"(r[3]) : "r"(saddr));
}

__device__ __forceinline__ void cp_async16(uint32_t saddr, const void* gptr) {
    asm volatile("cp.async.cg.shared.global [%0], [%1], 16;" :: "r"(saddr), "l"(gptr));
}
#define CP_COMMIT() asm volatile("cp.async.commit_group;" ::: "memory")
// All groups older than the newest 1 are guaranteed complete after this.
#define CP_WAIT1()  asm volatile("cp.async.wait_group 1;" ::: "memory")

// ===========================================================================
// fp16 mma.sync GEMM: C[M x N] = epilogue(A[M x K] @ W[K x N] + bias)
//   Block tile 128 x 128, K-chunk 64, 3-stage cp.async, 256 threads,
//   2 CTAs/SM (cross-CTA overlap of barriers/prologue/epilogue).
//   8 warps 2(M) x 4(N); warp tile 64 x 32 = 4x4 m16n8k16 tiles.
//   SMEM (32-bit words): Asw[128][36] (m-major k-pair words, pad 4)
//                        Bsw[32][136] (kpair-major packed {W[2k],W[2k+1]})
//   A frags via ldmatrix.x4; B frag word bank = (8c + g + nb) -> conflict-free.
//   Single __syncthreads per chunk:
//     iter i: wait_group(1) [group i complete] -> sync [all consumers of
//     slot (i-1)%3 done] -> issue into slot (i+2)%3 == (i-1)%3 -> compute i.
//   EPI 0: half( gamma*relu(z+bias)*INV_BN + beta )   -> __half C
//   EPI 1: z + bias                                   -> float C
// ===========================================================================
#define A_LDW  36
#define B_LDW  136
#define A_WORDS (128 * A_LDW)              // 4608
#define B_WORDS (32 * B_LDW)               // 4352
#define STAGE_WORDS (A_WORDS + B_WORDS)    // 8960
#define N_STAGES 3
#define SMEM_BYTES  (N_STAGES * STAGE_WORDS * 4)  // 107520 B per CTA

template <int EPI>
__global__ void __launch_bounds__(256, 2) mma_gemm_h(
    const __half* __restrict__ A, int lda,          // lda in halves
    const uint32_t* __restrict__ Wp, int ldbw,      // packed words per row
    void* __restrict__ Cv, int ldc, int K,
    const float* __restrict__ bias,
    const float* __restrict__ gamma,
    const float* __restrict__ beta)
{
    extern __shared__ uint32_t smw[];
    const int tid = threadIdx.x;
    const int wid = tid >> 5;
    const int lane = tid & 31;
    const int g = lane >> 2;           // 0..7
    const int c = lane & 3;            // 0..3
    const int wm = wid >> 2;           // 0..1 -> 64 rows
    const int wn = wid & 3;            // 0..3 -> 32 cols
    const int row0 = blockIdx.y * 128;
    const int col0 = blockIdx.x * 128;
    const int NK = K / 64;

    // cp.async staging
    const int am  = tid >> 3;          // A row 0..31 (x4 -> 128)
    const int akc = (tid & 7) * 4;     // A word-chunk (4 words = 8 halves)
    const int bkp = tid >> 5;          // B kpair-row 0..7 (x4 -> 32)
    const int bnc = (tid & 31) * 4;    // B word-chunk 0..124

    // ldmatrix lane mapping
    const int lq = lane >> 3, lr = lane & 7;
    const int lm_off = ((lq & 1) * 8 + lr) * A_LDW + (lq >> 1) * 4;  // words

    uint32_t smem_u32;
    {
        uint64_t t = __cvta_generic_to_shared(smw);
        smem_u32 = (uint32_t)t;
    }

    float acc[4][4][4];
#pragma unroll
    for (int i = 0; i < 4; ++i)
#pragma unroll
        for (int j = 0; j < 4; ++j)
#pragma unroll
            for (int q = 0; q < 4; ++q) acc[i][j][q] = 0.0f;

    auto issue_stage = [&](int s, int kt) {            // kt in k-halves
        const uint32_t abase = smem_u32 + (uint32_t)(s * STAGE_WORDS) * 4u;
        const uint32_t bbase = abase + A_WORDS * 4u;
#pragma unroll
        for (int it = 0; it < 4; ++it) {
            const int m = am + it * 32;
            cp_async16(abase + (uint32_t)(m * A_LDW + akc) * 4u,
                       A + (size_t)(row0 + m) * lda + kt + akc * 2);
        }
#pragma unroll
        for (int it = 0; it < 4; ++it) {
            const int kp = bkp + it * 8;
            cp_async16(bbase + (uint32_t)(kp * B_LDW + bnc) * 4u,
                       Wp + (size_t)(kt / 2 + kp) * ldbw + col0 + bnc);
        }
    };

    // prologue: prefetch stages 0,1 (commit always, for group accounting)
#pragma unroll
    for (int j = 0; j < N_STAGES - 1; ++j) {
        if (j < NK) issue_stage(j, j * 64);
        CP_COMMIT();
    }

    for (int i = 0; i < NK; ++i) {
        CP_WAIT1();            // group i complete (only group i+1 may pend)
        __syncthreads();       // consumers of slot (i-1)%3 are done

        if (i + N_STAGES - 1 < NK)
            issue_stage((i + N_STAGES - 1) % N_STAGES, (i + N_STAGES - 1) * 64);
        CP_COMMIT();

        const int s = i % N_STAGES;
        const uint32_t a_stage = smem_u32 + (uint32_t)(s * STAGE_WORDS) * 4u;
        const uint32_t* Bsw = smw + s * STAGE_WORDS + A_WORDS;   // [32][136]

#pragma unroll
        for (int ksw = 0; ksw < 32; ksw += 8) {                  // 4 ksteps of k16
            uint32_t af[4][4], bf[4][2];
#pragma unroll
            for (int mt = 0; mt < 4; ++mt) {
                const int rb = wm * 64 + mt * 16;
                ldmatrix_x4(af[mt],
                            a_stage + (uint32_t)(rb * A_LDW + ksw + lm_off) * 4u);
            }
#pragma unroll
            for (int nt = 0; nt < 4; ++nt) {
                const int nb = wn * 32 + nt * 8;
                bf[nt][0] = Bsw[(ksw + c)     * B_LDW + nb + g];
                bf[nt][1] = Bsw[(ksw + c + 4) * B_LDW + nb + g];
            }
#pragma unroll
            for (int mt = 0; mt < 4; ++mt)
#pragma unroll
                for (int nt = 0; nt < 4; ++nt)
                    mma_f16(acc[mt][nt], af[mt], bf[nt]);
        }
    }

    // ---- epilogue ----
#pragma unroll
    for (int mt = 0; mt < 4; ++mt) {
        const int r0 = row0 + wm * 64 + mt * 16 + g;
#pragma unroll
        for (int nt = 0; nt < 4; ++nt) {
            const int cb = col0 + wn * 32 + nt * 8 + 2 * c;
            float z[4];
            z[0] = acc[mt][nt][0] + __ldg(&bias[cb]);
            z[1] = acc[mt][nt][1] + __ldg(&bias[cb + 1]);
            z[2] = acc[mt][nt][2] + __ldg(&bias[cb]);
            z[3] = acc[mt][nt][3] + __ldg(&bias[cb + 1]);
            if (EPI == 0) {
                const float ga0 = __ldg(&gamma[cb]),     be0  = __ldg(&beta[cb]);
                const float ga1 = __ldg(&gamma[cb + 1]), be1v = __ldg(&beta[cb + 1]);
                z[0] = ga0 * fmaxf(z[0], 0.0f) * INV_BN + be0;
                z[1] = ga1 * fmaxf(z[1], 0.0f) * INV_BN + be1v;
                z[2] = ga0 * fmaxf(z[2], 0.0f) * INV_BN + be0;
                z[3] = ga1 * fmaxf(z[3], 0.0f) * INV_BN + be1v;
                __half* C = (__half*)Cv;
                *(__half2*)&C[(size_t)r0 * ldc + cb]       = __floats2half2_rn(z[0], z[1]);
                *(__half2*)&C[(size_t)(r0 + 8) * ldc + cb] = __floats2half2_rn(z[2], z[3]);
            } else {
                float* C = (float*)Cv;
                *(float2*)&C[(size_t)r0 * ldc + cb]       = make_float2(z[0], z[1]);
                *(float2*)&C[(size_t)(r0 + 8) * ldc + cb] = make_float2(z[2], z[3]);
            }
        }
    }
}

// ===========================================================================
// Prep kernels
// ===========================================================================
__global__ void pack_x_kernel(const float* __restrict__ x, __half* __restrict__ xe)
{
    const int i = blockIdx.x * 256 + threadIdx.x;   // over B_ROWS*64
    const int row = i >> 6, j = i & 63;
    xe[i] = __float2half_rn(x[(size_t)row * IN_DIM + 2 * j]);
}

// pack W[K][N] fp32 -> [K/2][N] uint32 words {h(W[2kp][n]), h(W[2kp+1][n])}
__global__ void pack_w_kernel(const float* __restrict__ W, uint32_t* __restrict__ out,
                              int K2, int N)
{
    const int i = blockIdx.x * 256 + threadIdx.x;
    if (i >= K2 * N) return;
    const int kp = i / N, n = i - kp * N;
    const __half lo = __float2half_rn(W[(size_t)(2 * kp) * N + n]);
    const __half hi = __float2half_rn(W[(size_t)(2 * kp + 1) * N + n]);
    out[i] = (uint32_t)__half_as_ushort(lo) | ((uint32_t)__half_as_ushort(hi) << 16);
}

// ===========================================================================
// RQ-spline + scatter epilogue
// ===========================================================================
__global__ __launch_bounds__(256) void spline_kernel(
    const float* __restrict__ x,
    const float* __restrict__ params,
    float* __restrict__ out,
    float* __restrict__ logdet)
{
    const int tid = threadIdx.x;
    const int row = blockIdx.x * 4 + (tid >> 6);
    const int j = tid & 63;
    const float* p = params + (size_t)row * DOUT + j * 24;

    float wr[NBINS], hr[NBINS], drw[NBINS];
#pragma unroll
    for (int k = 0; k < NBINS; ++k) wr[k] = p[k];
#pragma unroll
    for (int k = 0; k < NBINS; ++k) hr[k] = p[NBINS + k];
#pragma unroll
    for (int k = 0; k < NBINS; ++k) drw[k] = p[2 * NBINS + k];

    const float xi = x[(size_t)row * IN_DIM + 2 * j + 1];
    const float xt = x[(size_t)row * IN_DIM + 2 * j];

    float cw[NBINS + 1], ch[NBINS + 1], dd[NBINS + 1];
    {
        float m = wr[0];
#pragma unroll
        for (int k = 1; k < NBINS; ++k) m = fmaxf(m, wr[k]);
        float e[NBINS], s = 0.0f;
#pragma unroll
        for (int k = 0; k < NBINS; ++k) { e[k] = expf(wr[k] - m); s += e[k]; }
        const float inv = 1.0f / s;
        cw[0] = 0.0f;
#pragma unroll
        for (int k = 0; k < NBINS; ++k)
            cw[k + 1] = cw[k] + (MIN_W + (1.0f - MIN_W * NBINS) * e[k] * inv);
    }
    {
        float m = hr[0];
#pragma unroll
        for (int k = 1; k < NBINS; ++k) m = fmaxf(m, hr[k]);
        float e[NBINS], s = 0.0f;
#pragma unroll
        for (int k = 0; k < NBINS; ++k) { e[k] = expf(hr[k] - m); s += e[k]; }
        const float inv = 1.0f / s;
        ch[0] = 0.0f;
#pragma unroll
        for (int k = 0; k < NBINS; ++k)
            ch[k + 1] = ch[k] + (MIN_H + (1.0f - MIN_H * NBINS) * e[k] * inv);
    }
#pragma unroll
    for (int k = 0; k < NBINS; ++k) {
        const float v = drw[k];
        dd[k] = MIN_D + (fmaxf(v, 0.0f) + log1pf(expf(-fabsf(v))));
    }
    dd[NBINS] = MIN_D;

    int bin = 0;
#pragma unroll
    for (int k = 0; k < NBINS; ++k) bin += (xi > cw[k]) ? 1 : 0;
    bin = min(max(bin, 0), NBINS - 1);

    const float xl = cw[bin], xr = cw[bin + 1];
    const float yl = ch[bin], yr = ch[bin + 1];
    const float bw = xr - xl, bh = yr - yl;
    const float dl = dd[bin], dr = dd[bin + 1];

    float t = (xi - xl) / bw;
    t = fminf(fmaxf(t, 0.0f), 1.0f);

    const float num = bh * (dl * t * t + 2.0f * t * (1.0f - t));
    const float den = dl + (dr - dl) * t;
    const float yv = yl + num / den;
    const float ld = logf(bh) + 2.0f * logf(2.0f * t * (1.0f - t) * dr + dl) - logf(den);

    out[(size_t)row * IN_DIM + 2 * j] = xt;
    out[(size_t)row * IN_DIM + 2 * j + 1] = yv;

    __shared__ float red[256];
    red[tid] = ld;
    __syncthreads();
    for (int s = 32; s > 0; s >>= 1) {
        if ((tid & 63) < s) red[tid] += red[tid + s];
        __syncthreads();
    }
    if ((tid & 63) == 0) logdet[row] = red[tid];
}

// ===========================================================================
// Host side
// ===========================================================================
extern "C" void kernel_launch(void* const* d_in, const int* in_sizes, int n_in,
                              void* d_out, int out_size)
{
    const float* x   = (const float*)d_in[0];
    const float* W1  = (const float*)d_in[1];
    const float* b1  = (const float*)d_in[2];
    const float* g1  = (const float*)d_in[3];
    const float* be1 = (const float*)d_in[4];
    const float* W2  = (const float*)d_in[5];
    const float* b2  = (const float*)d_in[6];
    const float* g2  = (const float*)d_in[7];
    const float* be2 = (const float*)d_in[8];
    const float* W3  = (const float*)d_in[9];
    const float* b3  = (const float*)d_in[10];

    float* out    = (float*)d_out;
    float* logdet = out + (size_t)B_ROWS * IN_DIM;

    __half *h1, *h2, *xe;
    float *pp;
    uint32_t *w1p, *w2p, *w3p;
    cudaGetSymbolAddress((void**)&h1,  g_h1);
    cudaGetSymbolAddress((void**)&h2,  g_h2);
    cudaGetSymbolAddress((void**)&pp,  g_params);
    cudaGetSymbolAddress((void**)&xe,  g_xe);
    cudaGetSymbolAddress((void**)&w1p, g_w1p);
    cudaGetSymbolAddress((void**)&w2p, g_w2p);
    cudaGetSymbolAddress((void**)&w3p, g_w3p);

    cudaFuncSetAttribute(mma_gemm_h<0>, cudaFuncAttributeMaxDynamicSharedMemorySize, SMEM_BYTES);
    cudaFuncSetAttribute(mma_gemm_h<1>, cudaFuncAttributeMaxDynamicSharedMemorySize, SMEM_BYTES);

    // Prep: pack x even cols + k-pair-interleave weights (all fp16)
    pack_x_kernel<<<(B_ROWS * 64) / 256, 256>>>(x, xe);
    pack_w_kernel<<<(32   * HDIM + 255) / 256, 256>>>(W1, w1p, 32,   HDIM);
    pack_w_kernel<<<(1024 * HDIM + 255) / 256, 256>>>(W2, w2p, 1024, HDIM);
    pack_w_kernel<<<(1024 * DOUT + 255) / 256, 256>>>(W3, w3p, 1024, DOUT);

    // GEMM1: [32768 x 64] @ [64 x 2048] -> h1 (fp16)
    mma_gemm_h<0><<<dim3(HDIM / 128, B_ROWS / 128), 256, SMEM_BYTES>>>(
        xe, 64, w1p, HDIM, h1, HDIM, 64, b1, g1, be1);
    // GEMM2: [32768 x 2048] @ [2048 x 2048] -> h2 (fp16)
    mma_gemm_h<0><<<dim3(HDIM / 128, B_ROWS / 128), 256, SMEM_BYTES>>>(
        h1, HDIM, w2p, HDIM, h2, HDIM, HDIM, b2, g2, be2);
    // GEMM3: [32768 x 2048] @ [2048 x 1536] -> params (fp32)
    mma_gemm_h<1><<<dim3(DOUT / 128, B_ROWS / 128), 256, SMEM_BYTES>>>(
        h2, HDIM, w3p, DOUT, pp, DOUT, HDIM, b3, (const float*)0, (const float*)0);

    // Spline + scatter + log_det
    spline_kernel<<<B_ROWS / 4, 256>>>(x, pp, out, logdet);
}